// round 8
// baseline (speedup 1.0000x reference)
#include <cuda_runtime.h>
#include <cuda_bf16.h>

#define LOG2E 1.4426950408889634f

typedef unsigned long long u64;

__device__ __forceinline__ u64 pk2(float lo, float hi) {
    u64 r; asm("mov.b64 %0, {%1, %2};" : "=l"(r) : "f"(lo), "f"(hi)); return r;
}
__device__ __forceinline__ u64 ffma2(u64 a, u64 b, u64 c) {
    u64 d; asm("fma.rn.f32x2 %0, %1, %2, %3;" : "=l"(d) : "l"(a), "l"(b), "l"(c)); return d;
}
__device__ __forceinline__ u64 fadd2(u64 a, u64 b) {
    u64 d; asm("add.rn.f32x2 %0, %1, %2;" : "=l"(d) : "l"(a), "l"(b)); return d;
}
__device__ __forceinline__ float sqrt_ap(float x) {
    float d; asm("sqrt.approx.f32 %0, %1;" : "=f"(d) : "f"(x)); return d;
}
__device__ __forceinline__ float ex2_ap(float x) {
    float e; asm("ex2.approx.f32 %0, %1;" : "=f"(e) : "f"(x)); return e;
}

// Packed squared distance for one atom pair: s = qn + pw - 2 q.p  (both halves)
#define DIST2(PA, PB) \
    ffma2(m2x2, (PA).x, ffma2(m2y2, (PA).y, ffma2(m2z2, (PB).x, fadd2((PB).y, qn2))))

// Fused epilogue for one packed pair: unpack (register alias, free), abs
// (adjacent to sqrt -> folds into MUFU |src| modifier), sqrt, ex2, accumulate.
// One asm scope = no cross-boundary MOV/FMNMX/LOP glue.
#define MUFU_ACC(u, a0, a1)                                          \
    asm("{\n\t"                                                      \
        ".reg .f32 lo, hi;\n\t"                                      \
        "mov.b64 {lo, hi}, %2;\n\t"                                  \
        "abs.f32 lo, lo;\n\t"                                        \
        "abs.f32 hi, hi;\n\t"                                        \
        "sqrt.approx.f32 lo, lo;\n\t"                                \
        "sqrt.approx.f32 hi, hi;\n\t"                                \
        "ex2.approx.f32 lo, lo;\n\t"                                 \
        "ex2.approx.f32 hi, hi;\n\t"                                 \
        "add.f32 %0, %0, lo;\n\t"                                    \
        "add.f32 %1, %1, hi;\n\t"                                    \
        "}" : "+f"(a0), "+f"(a1) : "l"(u))

#define GPB 128  // grid points per block; 256 threads = 2 atom-halves per g

__global__ __launch_bounds__(256, 8)
void initlayer_kernel(const float* __restrict__ R,
                      const float* __restrict__ coords,
                      const float* __restrict__ W,
                      float* __restrict__ out,
                      int A, int G) {
    // Pair-packed atoms, 32B per pair:
    //   [2p]  .x=(px0,px1) .y=(py0,py1)   [2p+1] .x=(pz0,pz1) .y=(pw0,pw1)
    extern __shared__ float smem[];
    const ulonglong2* smp = (const ulonglong2*)smem;
    float* red = smem + ((A + 1) / 2) * 8;

    const int tid  = threadIdx.x;
    const int b    = blockIdx.y;
    const int gl   = tid & (GPB - 1);
    const int half = tid >> 7;
    const int g    = blockIdx.x * GPB + gl;

    // Weight pre-scaled by log2(e): exp(||W(c-r)||) == ex2(||W'(c-r)||).
    const float w00 = W[0] * LOG2E, w01 = W[1] * LOG2E, w02 = W[2] * LOG2E;
    const float w10 = W[3] * LOG2E, w11 = W[4] * LOG2E, w12 = W[5] * LOG2E;
    const float w20 = W[6] * LOG2E, w21 = W[7] * LOG2E, w22 = W[8] * LOG2E;

    // Prologue: transform atoms, store pair-packed (p', |p'|^2).
    for (int a = tid; a < A; a += blockDim.x) {
        const float* r = R + ((long)b * A + a) * 3;
        float rx = r[0], ry = r[1], rz = r[2];
        float px = fmaf(w00, rx, fmaf(w01, ry, w02 * rz));
        float py = fmaf(w10, rx, fmaf(w11, ry, w12 * rz));
        float pz = fmaf(w20, rx, fmaf(w21, ry, w22 * rz));
        float pw = fmaf(px, px, fmaf(py, py, pz * pz));
        float* base = smem + (a >> 1) * 8;
        int h = a & 1;
        base[0 + h] = px;
        base[2 + h] = py;
        base[4 + h] = pz;
        base[6 + h] = pw;
    }
    __syncthreads();

    float result = 0.0f;
    if (g < G) {
        const float cx = coords[g * 3 + 0];
        const float cy = coords[g * 3 + 1];
        const float cz = coords[g * 3 + 2];
        const float qx = fmaf(w00, cx, fmaf(w01, cy, w02 * cz));
        const float qy = fmaf(w10, cx, fmaf(w11, cy, w12 * cz));
        const float qz = fmaf(w20, cx, fmaf(w21, cy, w22 * cz));
        const float qn = fmaf(qx, qx, fmaf(qy, qy, qz * qz));

        const u64 m2x2 = pk2(-2.0f * qx, -2.0f * qx);
        const u64 m2y2 = pk2(-2.0f * qy, -2.0f * qy);
        const u64 m2z2 = pk2(-2.0f * qz, -2.0f * qz);
        const u64 qn2  = pk2(qn, qn);

        // This thread's atom half [a0, a1); pair indices [p0, p1).
        const int ahalf = A >> 1;
        const int a0 = half ? ahalf : 0;
        const int a1 = half ? A : ahalf;
        const int p0 = (a0 + 1) >> 1;
        const int p1 = a1 >> 1;

        float acc0 = 0.0f, acc1 = 0.0f, acc2 = 0.0f, acc3 = 0.0f;

        int p = p0;
        #pragma unroll 4
        for (; p + 2 <= p1; p += 2) {
            {
                ulonglong2 PA = smp[2 * p + 0], PB = smp[2 * p + 1];
                u64 u = DIST2(PA, PB);
                MUFU_ACC(u, acc0, acc1);
            }
            {
                ulonglong2 PA = smp[2 * p + 2], PB = smp[2 * p + 3];
                u64 u = DIST2(PA, PB);
                MUFU_ACC(u, acc2, acc3);
            }
        }
        for (; p < p1; ++p) {
            ulonglong2 PA = smp[2 * p + 0], PB = smp[2 * p + 1];
            u64 u = DIST2(PA, PB);
            MUFU_ACC(u, acc0, acc1);
        }
        // Scalar tails (odd boundaries; no-ops when half-ranges are even).
        for (int a = a0; a < 2 * p0 && a < a1; ++a) {
            const float* base = smem + (a >> 1) * 8;
            int h = a & 1;
            float s = fmaf(-2.0f * qx, base[0 + h],
                      fmaf(-2.0f * qy, base[2 + h],
                      fmaf(-2.0f * qz, base[4 + h], qn + base[6 + h])));
            acc0 += ex2_ap(sqrt_ap(fabsf(s)));
        }
        for (int a = (2 * p1 > a0 ? 2 * p1 : a0); a < a1; ++a) {
            const float* base = smem + (a >> 1) * 8;
            int h = a & 1;
            float s = fmaf(-2.0f * qx, base[0 + h],
                      fmaf(-2.0f * qy, base[2 + h],
                      fmaf(-2.0f * qz, base[4 + h], qn + base[6 + h])));
            acc0 += ex2_ap(sqrt_ap(fabsf(s)));
        }
        result = (acc0 + acc1) + (acc2 + acc3);
    }

    // Combine the two atom-half partials; single writer per g.
    if (half == 1) red[gl] = result;
    __syncthreads();
    if (half == 0 && g < G) {
        out[(long)b * G + g] = result + red[gl];
    }
}

extern "C" void kernel_launch(void* const* d_in, const int* in_sizes, int n_in,
                              void* d_out, int out_size) {
    const float* R      = (const float*)d_in[0];  // (B, A, 3) f32
    const float* coords = (const float*)d_in[1];  // (G, 3)    f32
    const float* W      = (const float*)d_in[2];  // (3, 3)    f32

    const int A = in_sizes[3];
    const int B = in_sizes[0] / (3 * A);
    const int G = in_sizes[1] / 3;

    float* out = (float*)d_out;  // (B, G) f32

    dim3 grid((G + GPB - 1) / GPB, B);
    size_t smem = (size_t)((A + 1) / 2) * 8 * sizeof(float) + GPB * sizeof(float);

    initlayer_kernel<<<grid, 256, smem>>>(R, coords, W, out, A, G);
}

// round 9
// speedup vs baseline: 1.5893x; 1.5893x over previous
#include <cuda_runtime.h>
#include <cuda_bf16.h>

#define LOG2E 1.4426950408889634f

typedef unsigned long long u64;

__device__ __forceinline__ u64 pk2(float lo, float hi) {
    u64 r; asm("mov.b64 %0, {%1, %2};" : "=l"(r) : "f"(lo), "f"(hi)); return r;
}
__device__ __forceinline__ u64 ffma2(u64 a, u64 b, u64 c) {
    u64 d; asm("fma.rn.f32x2 %0, %1, %2, %3;" : "=l"(d) : "l"(a), "l"(b), "l"(c)); return d;
}
__device__ __forceinline__ u64 fadd2(u64 a, u64 b) {
    u64 d; asm("add.rn.f32x2 %0, %1, %2;" : "=l"(d) : "l"(a), "l"(b)); return d;
}
__device__ __forceinline__ float sqrt_ap(float x) {
    float d; asm("sqrt.approx.f32 %0, %1;" : "=f"(d) : "f"(x)); return d;
}
__device__ __forceinline__ float ex2_ap(float x) {
    float e; asm("ex2.approx.f32 %0, %1;" : "=f"(e) : "f"(x)); return e;
}
__device__ __forceinline__ void upk2(float& lo, float& hi, u64 v) {
    asm("mov.b64 {%0, %1}, %2;" : "=f"(lo), "=f"(hi) : "l"(v));
}

// Packed squared distance for one atom pair: s = qn + pw - 2 q.p  (both halves)
#define DIST2(PA, PB) \
    ffma2(m2x2, (PA).x, ffma2(m2y2, (PA).y, ffma2(m2z2, (PB).x, fadd2((PB).y, qn2))))

#define GPB 128  // grid points per block; 256 threads = 2 atom-halves per g

__global__ __launch_bounds__(256, 8)
void initlayer_kernel(const float* __restrict__ R,
                      const float* __restrict__ coords,
                      const float* __restrict__ W,
                      float* __restrict__ out,
                      int A, int G) {
    // Pair-packed atoms, 32B per pair:
    //   [2p]  .x=(px0,px1) .y=(py0,py1)   [2p+1] .x=(pz0,pz1) .y=(pw0,pw1)
    extern __shared__ float smem[];
    const ulonglong2* smp = (const ulonglong2*)smem;
    float* red = smem + ((A + 1) / 2) * 8;

    const int tid  = threadIdx.x;
    const int b    = blockIdx.y;
    const int gl   = tid & (GPB - 1);
    const int half = tid >> 7;
    const int g    = blockIdx.x * GPB + gl;

    // Weight pre-scaled by log2(e): exp(||W(c-r)||) == ex2(||W'(c-r)||).
    const float w00 = W[0] * LOG2E, w01 = W[1] * LOG2E, w02 = W[2] * LOG2E;
    const float w10 = W[3] * LOG2E, w11 = W[4] * LOG2E, w12 = W[5] * LOG2E;
    const float w20 = W[6] * LOG2E, w21 = W[7] * LOG2E, w22 = W[8] * LOG2E;

    // Prologue: transform atoms, store pair-packed (p', |p'|^2).
    for (int a = tid; a < A; a += blockDim.x) {
        const float* r = R + ((long)b * A + a) * 3;
        float rx = r[0], ry = r[1], rz = r[2];
        float px = fmaf(w00, rx, fmaf(w01, ry, w02 * rz));
        float py = fmaf(w10, rx, fmaf(w11, ry, w12 * rz));
        float pz = fmaf(w20, rx, fmaf(w21, ry, w22 * rz));
        float pw = fmaf(px, px, fmaf(py, py, pz * pz));
        float* base = smem + (a >> 1) * 8;
        int h = a & 1;
        base[0 + h] = px;
        base[2 + h] = py;
        base[4 + h] = pz;
        base[6 + h] = pw;
    }
    __syncthreads();

    float result = 0.0f;
    if (g < G) {
        const float cx = coords[g * 3 + 0];
        const float cy = coords[g * 3 + 1];
        const float cz = coords[g * 3 + 2];
        const float qx = fmaf(w00, cx, fmaf(w01, cy, w02 * cz));
        const float qy = fmaf(w10, cx, fmaf(w11, cy, w12 * cz));
        const float qz = fmaf(w20, cx, fmaf(w21, cy, w22 * cz));
        const float qn = fmaf(qx, qx, fmaf(qy, qy, qz * qz));

        const u64 m2x2 = pk2(-2.0f * qx, -2.0f * qx);
        const u64 m2y2 = pk2(-2.0f * qy, -2.0f * qy);
        const u64 m2z2 = pk2(-2.0f * qz, -2.0f * qz);
        const u64 qn2  = pk2(qn, qn);

        float acc[8];
        #pragma unroll
        for (int i = 0; i < 8; ++i) acc[i] = 0.0f;

        if (A == 256) {
            // Specialized path: 128 atoms per thread = 64 pairs, constant trips,
            // no tails. 8 independent accumulator chains for MUFU latency hiding.
            const ulonglong2* tp = smp + half * 128;  // 64 pairs * 2 u64x2 each
            #pragma unroll 16
            for (int p = 0; p < 64; ++p) {
                ulonglong2 PA = tp[2 * p + 0], PB = tp[2 * p + 1];
                u64 u = DIST2(PA, PB);
                float s0, s1; upk2(s0, s1, u);
                acc[(2 * p) & 7]     += ex2_ap(sqrt_ap(fabsf(s0)));
                acc[(2 * p + 1) & 7] += ex2_ap(sqrt_ap(fabsf(s1)));
            }
        } else {
            // Generic path.
            const int ahalf = A >> 1;
            const int a0 = half ? ahalf : 0;
            const int a1 = half ? A : ahalf;
            const int p0 = (a0 + 1) >> 1;
            const int p1 = a1 >> 1;
            int p = p0;
            #pragma unroll 4
            for (; p < p1; ++p) {
                ulonglong2 PA = smp[2 * p + 0], PB = smp[2 * p + 1];
                u64 u = DIST2(PA, PB);
                float s0, s1; upk2(s0, s1, u);
                acc[(2 * p) & 7]     += ex2_ap(sqrt_ap(fabsf(s0)));
                acc[(2 * p + 1) & 7] += ex2_ap(sqrt_ap(fabsf(s1)));
            }
            for (int a = a0; a < 2 * p0 && a < a1; ++a) {
                const float* base = smem + (a >> 1) * 8;
                int h = a & 1;
                float s = fmaf(-2.0f * qx, base[0 + h],
                          fmaf(-2.0f * qy, base[2 + h],
                          fmaf(-2.0f * qz, base[4 + h], qn + base[6 + h])));
                acc[0] += ex2_ap(sqrt_ap(fabsf(s)));
            }
            for (int a = (2 * p1 > a0 ? 2 * p1 : a0); a < a1; ++a) {
                const float* base = smem + (a >> 1) * 8;
                int h = a & 1;
                float s = fmaf(-2.0f * qx, base[0 + h],
                          fmaf(-2.0f * qy, base[2 + h],
                          fmaf(-2.0f * qz, base[4 + h], qn + base[6 + h])));
                acc[0] += ex2_ap(sqrt_ap(fabsf(s)));
            }
        }

        result = ((acc[0] + acc[1]) + (acc[2] + acc[3]))
               + ((acc[4] + acc[5]) + (acc[6] + acc[7]));
    }

    // Combine the two atom-half partials; single writer per g.
    if (half == 1) red[gl] = result;
    __syncthreads();
    if (half == 0 && g < G) {
        out[(long)b * G + g] = result + red[gl];
    }
}

extern "C" void kernel_launch(void* const* d_in, const int* in_sizes, int n_in,
                              void* d_out, int out_size) {
    const float* R      = (const float*)d_in[0];  // (B, A, 3) f32
    const float* coords = (const float*)d_in[1];  // (G, 3)    f32
    const float* W      = (const float*)d_in[2];  // (3, 3)    f32

    const int A = in_sizes[3];
    const int B = in_sizes[0] / (3 * A);
    const int G = in_sizes[1] / 3;

    float* out = (float*)d_out;  // (B, G) f32

    dim3 grid((G + GPB - 1) / GPB, B);
    size_t smem = (size_t)((A + 1) / 2) * 8 * sizeof(float) + GPB * sizeof(float);

    initlayer_kernel<<<grid, 256, smem>>>(R, coords, W, out, A, G);
}